// round 1
// baseline (speedup 1.0000x reference)
#include <cuda_runtime.h>
#include <cuda_bf16.h>
#include <math.h>

// Problem constants
#define BB   4
#define TT   2048
#define CC   1024
#define HH   16
#define DD   64
#define BHTD (BB * HH * TT * DD)       // 8,388,608 elems per q/k/v buffer

// Scratch (device globals: alloc-free per harness rules)
__device__ float g_qkv[3ull * BHTD];                 // [3][B,H,T,D]
__device__ float g_att[(size_t)BB * TT * CC];        // [B,T,C] attention output

// ============================================================================
// SGEMM: C[m,n] = sum_k A[m,k] * Bt[n,k] + bias[n]
// Both A and Bt are K-contiguous row-major ([M,K] and [N,K]).
// mode 0: plain store to Cout[m*N+n]
// mode 1: scatter into g_qkv (QKV projection epilogue)
// mode 2: A := g_att (proj input), plain store
// ============================================================================
#define GBM 128
#define GBN 128
#define GBK 16
#define GPAD 4

__global__ __launch_bounds__(256) void sgemm_bias(
    const float* __restrict__ Ain, const float* __restrict__ Bt,
    const float* __restrict__ bias, float* __restrict__ Cout,
    int M, int N, int K, int mode)
{
    __shared__ float As[GBK][GBM + GPAD];
    __shared__ float Bs[GBK][GBN + GPAD];

    const float* A = (mode == 2) ? g_att : Ain;

    int tid = threadIdx.x;
    int tx = tid & 15, ty = tid >> 4;
    int m0 = blockIdx.y * GBM, n0 = blockIdx.x * GBN;

    float acc[8][8];
#pragma unroll
    for (int i = 0; i < 8; i++)
#pragma unroll
        for (int j = 0; j < 8; j++) acc[i][j] = 0.f;

    for (int k0 = 0; k0 < K; k0 += GBK) {
        // Load tiles (vectorized along K, transposed into smem [k][m]/[k][n])
#pragma unroll
        for (int it = 0; it < 2; it++) {
            int l = tid + it * 256;           // 0..511
            int row = l >> 2;                 // 0..127
            int kq  = (l & 3) << 2;           // 0,4,8,12
            float4 va = *(const float4*)(A  + (size_t)(m0 + row) * K + k0 + kq);
            As[kq + 0][row] = va.x; As[kq + 1][row] = va.y;
            As[kq + 2][row] = va.z; As[kq + 3][row] = va.w;
            float4 vb = *(const float4*)(Bt + (size_t)(n0 + row) * K + k0 + kq);
            Bs[kq + 0][row] = vb.x; Bs[kq + 1][row] = vb.y;
            Bs[kq + 2][row] = vb.z; Bs[kq + 3][row] = vb.w;
        }
        __syncthreads();

#pragma unroll
        for (int kk = 0; kk < GBK; kk++) {
            float a[8], b[8];
            *(float4*)&a[0] = *(const float4*)&As[kk][ty * 8];
            *(float4*)&a[4] = *(const float4*)&As[kk][ty * 8 + 4];
            *(float4*)&b[0] = *(const float4*)&Bs[kk][tx * 8];
            *(float4*)&b[4] = *(const float4*)&Bs[kk][tx * 8 + 4];
#pragma unroll
            for (int i = 0; i < 8; i++)
#pragma unroll
                for (int j = 0; j < 8; j++)
                    acc[i][j] += a[i] * b[j];
        }
        __syncthreads();
    }

    // Epilogue: bias add + store
#pragma unroll
    for (int i = 0; i < 8; i++) {
        int m = m0 + ty * 8 + i;
#pragma unroll
        for (int j = 0; j < 8; j += 4) {
            int n = n0 + tx * 8 + j;
            float4 r;
            r.x = acc[i][j + 0] + bias[n + 0];
            r.y = acc[i][j + 1] + bias[n + 1];
            r.z = acc[i][j + 2] + bias[n + 2];
            r.w = acc[i][j + 3] + bias[n + 3];
            if (mode == 1) {
                // n = which*1024 + h*64 + d ; m = b*2048 + t
                int which = n >> 10;
                int h = (n >> 6) & (HH - 1);
                int d = n & (DD - 1);
                int b = m >> 11;
                int t = m & (TT - 1);
                float* p = g_qkv + (size_t)which * BHTD
                         + ((((size_t)b * HH + h) * TT + t) * DD + d);
                *(float4*)p = r;
            } else {
                *(float4*)(Cout + (size_t)m * N + n) = r;
            }
        }
    }
}

// ============================================================================
// Flash attention (causal), fp32.
// Grid: (T/64, B*H). Block: 256 threads as 16x16, each owns a 4x4 tile.
// Smem: Qs [d][r] (scale 1/8 folded in), Ks [d][c] (aliased as P[n][r]),
//       Vs [n][d]. Stride 68 floats for bank-conflict avoidance.
// ============================================================================
#define AS 68
#define SMEM_ATTN (3 * 64 * AS * 4)

__global__ __launch_bounds__(256) void flash_attn()
{
    extern __shared__ float sm[];
    float* Qs = sm;                 // [64][AS]  layout [d][r]
    float* Ks = sm + 64 * AS;       // [64][AS]  layout [d][c], later P[n][r]
    float* Vs = sm + 2 * 64 * AS;   // [64][AS]  layout [n][d]

    int qb = blockIdx.x;
    int bh = blockIdx.y;
    int q0 = qb * 64;
    int tid = threadIdx.x, tx = tid & 15, ty = tid >> 4;

    const float* qp = g_qkv + (size_t)bh * TT * DD;
    const float* kp = g_qkv + (size_t)BHTD + (size_t)bh * TT * DD;
    const float* vp = g_qkv + 2ull * BHTD + (size_t)bh * TT * DD;

    // Load Q transposed, fold softmax scale D^-0.5 = 0.125
#pragma unroll
    for (int it = 0; it < 4; it++) {
        int l = tid + it * 256;     // 0..1023
        int row = l >> 4;           // 0..63
        int dq  = (l & 15) << 2;    // 0..60
        float4 v = *(const float4*)(qp + (size_t)(q0 + row) * DD + dq);
        Qs[(dq + 0) * AS + row] = v.x * 0.125f;
        Qs[(dq + 1) * AS + row] = v.y * 0.125f;
        Qs[(dq + 2) * AS + row] = v.z * 0.125f;
        Qs[(dq + 3) * AS + row] = v.w * 0.125f;
    }

    float m_i[4], l_i[4], acc[4][4];
#pragma unroll
    for (int i = 0; i < 4; i++) {
        m_i[i] = -1e30f; l_i[i] = 0.f;
#pragma unroll
        for (int j = 0; j < 4; j++) acc[i][j] = 0.f;
    }

    for (int jb = 0; jb <= qb; jb++) {
        int k0 = jb * 64;
        __syncthreads();  // prior PV reads of Ks/Vs done; also covers Q load on iter 0

        // Load K transposed [d][c] and V direct [n][d]
#pragma unroll
        for (int it = 0; it < 4; it++) {
            int l = tid + it * 256;
            int row = l >> 4;
            int dq  = (l & 15) << 2;
            float4 kv = *(const float4*)(kp + (size_t)(k0 + row) * DD + dq);
            Ks[(dq + 0) * AS + row] = kv.x;
            Ks[(dq + 1) * AS + row] = kv.y;
            Ks[(dq + 2) * AS + row] = kv.z;
            Ks[(dq + 3) * AS + row] = kv.w;
            float4 vv = *(const float4*)(vp + (size_t)(k0 + row) * DD + dq);
            *(float4*)&Vs[row * AS + dq] = vv;
        }
        __syncthreads();

        // S = (Q*scale) K^T   (4x4 per thread)
        float s[4][4];
#pragma unroll
        for (int i = 0; i < 4; i++)
#pragma unroll
            for (int j = 0; j < 4; j++) s[i][j] = 0.f;

#pragma unroll
        for (int d = 0; d < 64; d++) {
            float a[4], b[4];
            *(float4*)a = *(const float4*)&Qs[d * AS + ty * 4];
            *(float4*)b = *(const float4*)&Ks[d * AS + tx * 4];
#pragma unroll
            for (int i = 0; i < 4; i++)
#pragma unroll
                for (int j = 0; j < 4; j++)
                    s[i][j] += a[i] * b[j];
        }

        // Causal mask + online softmax (row groups = 16 consecutive lanes)
        bool diag = (jb == qb);
#pragma unroll
        for (int i = 0; i < 4; i++) {
            int qg = q0 + ty * 4 + i;
            float rm = -1e30f;
#pragma unroll
            for (int jj = 0; jj < 4; jj++) {
                if (diag && (k0 + tx * 4 + jj > qg)) s[i][jj] = -1e30f;
                rm = fmaxf(rm, s[i][jj]);
            }
#pragma unroll
            for (int off = 8; off; off >>= 1)
                rm = fmaxf(rm, __shfl_xor_sync(0xffffffffu, rm, off, 16));
            float mnew  = fmaxf(m_i[i], rm);
            float alpha = __expf(m_i[i] - mnew);
            float rs = 0.f;
#pragma unroll
            for (int jj = 0; jj < 4; jj++) {
                float p = __expf(s[i][jj] - mnew);
                s[i][jj] = p;
                rs += p;
            }
#pragma unroll
            for (int off = 8; off; off >>= 1)
                rs += __shfl_xor_sync(0xffffffffu, rs, off, 16);
            l_i[i] = l_i[i] * alpha + rs;
            m_i[i] = mnew;
#pragma unroll
            for (int jj = 0; jj < 4; jj++) acc[i][jj] *= alpha;
        }

        __syncthreads();  // everyone done reading Ks for S-gemm

        // Write P transposed into Ks buffer: P[n][r]
#pragma unroll
        for (int jj = 0; jj < 4; jj++)
#pragma unroll
            for (int i = 0; i < 4; i++)
                Ks[(tx * 4 + jj) * AS + ty * 4 + i] = s[i][jj];
        __syncthreads();

        // O += P V
#pragma unroll
        for (int n = 0; n < 64; n++) {
            float a[4], b[4];
            *(float4*)a = *(const float4*)&Ks[n * AS + ty * 4];
            *(float4*)b = *(const float4*)&Vs[n * AS + tx * 4];
#pragma unroll
            for (int i = 0; i < 4; i++)
#pragma unroll
                for (int j = 0; j < 4; j++)
                    acc[i][j] += a[i] * b[j];
        }
    }

    // Normalize + write to g_att in [B,T,C] layout
    int bb = bh >> 4, hh = bh & (HH - 1);
#pragma unroll
    for (int i = 0; i < 4; i++) {
        int qg = q0 + ty * 4 + i;
        float inv = 1.f / l_i[i];
        float4 r;
        r.x = acc[i][0] * inv;
        r.y = acc[i][1] * inv;
        r.z = acc[i][2] * inv;
        r.w = acc[i][3] * inv;
        *(float4*)(g_att + ((size_t)bb * TT + qg) * CC + hh * DD + tx * 4) = r;
    }
}

// ============================================================================
// Launch
// ============================================================================
extern "C" void kernel_launch(void* const* d_in, const int* in_sizes, int n_in,
                              void* d_out, int out_size)
{
    (void)in_sizes; (void)n_in; (void)out_size;
    const float* x      = (const float*)d_in[0];
    const float* qkv_w  = (const float*)d_in[1];
    const float* qkv_b  = (const float*)d_in[2];
    const float* proj_w = (const float*)d_in[3];
    const float* proj_b = (const float*)d_in[4];
    float* out = (float*)d_out;

    cudaFuncSetAttribute(flash_attn,
                         cudaFuncAttributeMaxDynamicSharedMemorySize, SMEM_ATTN);

    // 1) QKV projection + bias, scattered into [3][B,H,T,D]
    sgemm_bias<<<dim3(3 * CC / GBN, BB * TT / GBM), 256>>>(
        x, qkv_w, qkv_b, nullptr, BB * TT, 3 * CC, CC, 1);

    // 2) Causal flash attention -> g_att [B,T,C]
    flash_attn<<<dim3(TT / 64, BB * HH), 256, SMEM_ATTN>>>();

    // 3) Output projection + bias -> d_out
    sgemm_bias<<<dim3(CC / GBN, BB * TT / GBM), 256>>>(
        nullptr, proj_w, proj_b, out, BB * TT, CC, CC, 2);
}

// round 2
// speedup vs baseline: 2.1014x; 2.1014x over previous
#include <cuda_runtime.h>
#include <cuda_bf16.h>
#include <stdint.h>
#include <math.h>

// Problem constants
#define BB   4
#define TT   2048
#define CC   1024
#define HH   16
#define DD   64
#define BHTD (BB * HH * TT * DD)

// Scratch (device globals: alloc-free per harness rules)
__device__ float g_qkv[3ull * BHTD];            // [3][B,H,T,D]
__device__ float g_att[(size_t)BB * TT * CC];   // [B,T,C]

// ---------------------------------------------------------------------------
// tf32 helpers
// ---------------------------------------------------------------------------
__device__ __forceinline__ uint32_t f2tf(float x) {
    uint32_t u;
    asm("cvt.rna.tf32.f32 %0, %1;" : "=r"(u) : "f"(x));
    return u;
}
__device__ __forceinline__ float f2tff(float x) { return __uint_as_float(f2tf(x)); }

__device__ __forceinline__ void mma8(float* c,
    uint32_t a0, uint32_t a1, uint32_t a2, uint32_t a3,
    uint32_t b0, uint32_t b1)
{
    asm volatile(
        "mma.sync.aligned.m16n8k8.row.col.f32.tf32.tf32.f32 "
        "{%0,%1,%2,%3},{%4,%5,%6,%7},{%8,%9},{%0,%1,%2,%3};"
        : "+f"(c[0]), "+f"(c[1]), "+f"(c[2]), "+f"(c[3])
        : "r"(a0), "r"(a1), "r"(a2), "r"(a3), "r"(b0), "r"(b1));
}

// ===========================================================================
// TF32 tensor-core GEMM: C[m,n] = sum_k A[m,k]*Bt[n,k] + bias[n]
// Block tile 128x128x32, 8 warps, warp tile 32x64.
// mode 0: plain store; mode 1: QKV scatter; mode 2: A := g_att, plain store.
// ===========================================================================
#define GBM 128
#define GBN 128
#define GBK 32
#define SST 136   // smem stride: 136 mod 32 == 8 -> conflict-free frag loads

__global__ __launch_bounds__(256) void gemm_tc(
    const float* __restrict__ Ain, const float* __restrict__ Bt,
    const float* __restrict__ bias, float* __restrict__ Cout,
    int M, int N, int K, int mode)
{
    __shared__ float As[GBK * SST];   // [k][m], tf32 bit patterns
    __shared__ float Bs[GBK * SST];   // [k][n]

    const float* A = (mode == 2) ? g_att : Ain;
    const uint32_t* Asu = (const uint32_t*)As;
    const uint32_t* Bsu = (const uint32_t*)Bs;

    int tid = threadIdx.x, lane = tid & 31, w = tid >> 5;
    int wm0 = (w >> 1) * 32;        // 4 warps along M
    int wn0 = (w & 1) * 64;         // 2 warps along N
    int m0 = blockIdx.y * GBM, n0 = blockIdx.x * GBN;

    float acc[2][8][4];
#pragma unroll
    for (int mt = 0; mt < 2; mt++)
#pragma unroll
        for (int nt = 0; nt < 8; nt++)
#pragma unroll
            for (int j = 0; j < 4; j++) acc[mt][nt][j] = 0.f;

    for (int k0 = 0; k0 < K; k0 += GBK) {
        // Stage tiles: 128 rows x 32 k each, float4 gmem loads, cvt -> tf32
#pragma unroll
        for (int it = 0; it < 4; it++) {
            int l = tid + it * 256;       // 0..1023
            int row = l >> 3;             // 0..127
            int kq = (l & 7) * 4;         // 0..28
            float4 va = *(const float4*)(A + (size_t)(m0 + row) * K + k0 + kq);
            As[(kq + 0) * SST + row] = f2tff(va.x);
            As[(kq + 1) * SST + row] = f2tff(va.y);
            As[(kq + 2) * SST + row] = f2tff(va.z);
            As[(kq + 3) * SST + row] = f2tff(va.w);
            float4 vb = *(const float4*)(Bt + (size_t)(n0 + row) * K + k0 + kq);
            Bs[(kq + 0) * SST + row] = f2tff(vb.x);
            Bs[(kq + 1) * SST + row] = f2tff(vb.y);
            Bs[(kq + 2) * SST + row] = f2tff(vb.z);
            Bs[(kq + 3) * SST + row] = f2tff(vb.w);
        }
        __syncthreads();

#pragma unroll
        for (int kc = 0; kc < 4; kc++) {
            uint32_t a[2][4];
#pragma unroll
            for (int mt = 0; mt < 2; mt++) {
                int mb = wm0 + mt * 16 + (lane >> 2);
                a[mt][0] = Asu[(kc * 8 + (lane & 3)) * SST + mb];
                a[mt][1] = Asu[(kc * 8 + (lane & 3)) * SST + mb + 8];
                a[mt][2] = Asu[(kc * 8 + 4 + (lane & 3)) * SST + mb];
                a[mt][3] = Asu[(kc * 8 + 4 + (lane & 3)) * SST + mb + 8];
            }
#pragma unroll
            for (int nt = 0; nt < 8; nt++) {
                int nb = wn0 + nt * 8 + (lane >> 2);
                uint32_t b0 = Bsu[(kc * 8 + (lane & 3)) * SST + nb];
                uint32_t b1 = Bsu[(kc * 8 + 4 + (lane & 3)) * SST + nb];
                mma8(acc[0][nt], a[0][0], a[0][1], a[0][2], a[0][3], b0, b1);
                mma8(acc[1][nt], a[1][0], a[1][1], a[1][2], a[1][3], b0, b1);
            }
        }
        __syncthreads();
    }

    // Epilogue: bias + store (fragment layout: regs {0,1}=row, {2,3}=row+8)
#pragma unroll
    for (int mt = 0; mt < 2; mt++) {
#pragma unroll
        for (int h = 0; h < 2; h++) {
            int m = m0 + wm0 + mt * 16 + (lane >> 2) + h * 8;
#pragma unroll
            for (int nt = 0; nt < 8; nt++) {
                int n = n0 + wn0 + nt * 8 + 2 * (lane & 3);
                float2 r;
                r.x = acc[mt][nt][h * 2 + 0] + bias[n];
                r.y = acc[mt][nt][h * 2 + 1] + bias[n + 1];
                if (mode == 1) {
                    int which = n >> 10;
                    int hh = (n >> 6) & (HH - 1);
                    int d = n & (DD - 1);
                    int b = m >> 11;
                    int t = m & (TT - 1);
                    float* p = g_qkv + (size_t)which * BHTD
                             + ((((size_t)b * HH + hh) * TT + t) * DD + d);
                    *(float2*)p = r;
                } else {
                    *(float2*)(Cout + (size_t)m * N + n) = r;
                }
            }
        }
    }
}

// ===========================================================================
// Flash attention (causal) with tf32 tensor cores.
// Grid (T/128, B*H), 256 threads = 8 warps, each warp owns 16 q rows.
// Q pre-scaled (1/8) tf32 A-fragments in registers; K/V staged per k-block.
// ===========================================================================
#define KSD 68    // K smem stride (68 mod 32 == 4 -> conflict-free S B-frags)
#define VSD 72    // V smem stride (72 mod 32 == 8 -> conflict-free PV B-frags)
#define SMEM_ATTN ((64 * KSD + 64 * VSD + 8 * 16 * KSD) * 4)

__global__ __launch_bounds__(256) void attn_tc()
{
    extern __shared__ float sm[];
    float* Ksm = sm;                         // [64][KSD] tf32 [t][d]
    float* Vsm = sm + 64 * KSD;              // [64][VSD] tf32 [t][d]
    float* Psm = sm + 64 * KSD + 64 * VSD;   // 8 warps x [16][KSD] tf32
    const uint32_t* Ku = (const uint32_t*)Ksm;
    const uint32_t* Vu = (const uint32_t*)Vsm;

    int qb = gridDim.x - 1 - blockIdx.x;     // big blocks first
    int bh = blockIdx.y;
    int q0 = qb * 128;
    int tid = threadIdx.x, lane = tid & 31, w = tid >> 5;
    int qw0 = q0 + w * 16;

    const float* qp = g_qkv + (size_t)bh * TT * DD;
    const float* kp = qp + (size_t)BHTD;
    const float* vp = qp + 2ull * BHTD;

    // Q -> registers as A-fragments, scale folded
    uint32_t qa[8][4];
    {
        int r = qw0 + (lane >> 2);
#pragma unroll
        for (int c = 0; c < 8; c++) {
            int col = c * 8 + (lane & 3);
            qa[c][0] = f2tf(qp[(size_t)r * DD + col] * 0.125f);
            qa[c][1] = f2tf(qp[(size_t)(r + 8) * DD + col] * 0.125f);
            qa[c][2] = f2tf(qp[(size_t)r * DD + col + 4] * 0.125f);
            qa[c][3] = f2tf(qp[(size_t)(r + 8) * DD + col + 4] * 0.125f);
        }
    }

    float m_i[2] = {-1e30f, -1e30f}, l_i[2] = {0.f, 0.f};
    float oacc[8][4];
#pragma unroll
    for (int nt = 0; nt < 8; nt++)
#pragma unroll
        for (int j = 0; j < 4; j++) oacc[nt][j] = 0.f;

    int jbmax = 2 * qb + 1;
    for (int jb = 0; jb <= jbmax; jb++) {
        int k0 = jb * 64;
        __syncthreads();   // prior iteration done reading Ksm/Vsm
#pragma unroll
        for (int it = 0; it < 4; it++) {
            int l = tid + it * 256;
            int row = l >> 4;            // 0..63
            int dq = (l & 15) * 4;       // 0..60
            float4 kv = *(const float4*)(kp + (size_t)(k0 + row) * DD + dq);
            float4 kc;
            kc.x = f2tff(kv.x); kc.y = f2tff(kv.y);
            kc.z = f2tff(kv.z); kc.w = f2tff(kv.w);
            *(float4*)&Ksm[row * KSD + dq] = kc;
            float4 vv = *(const float4*)(vp + (size_t)(k0 + row) * DD + dq);
            float4 vc;
            vc.x = f2tff(vv.x); vc.y = f2tff(vv.y);
            vc.z = f2tff(vv.z); vc.w = f2tff(vv.w);
            *(float4*)&Vsm[row * VSD + dq] = vc;
        }
        __syncthreads();

        if (k0 <= qw0 + 15) {   // warp has at least one unmasked row
            // S = (Q/8) K^T
            float sacc[8][4];
#pragma unroll
            for (int nt = 0; nt < 8; nt++)
#pragma unroll
                for (int j = 0; j < 4; j++) sacc[nt][j] = 0.f;
#pragma unroll
            for (int kc = 0; kc < 8; kc++) {
#pragma unroll
                for (int nt = 0; nt < 8; nt++) {
                    uint32_t b0 = Ku[(nt * 8 + (lane >> 2)) * KSD + kc * 8 + (lane & 3)];
                    uint32_t b1 = Ku[(nt * 8 + (lane >> 2)) * KSD + kc * 8 + 4 + (lane & 3)];
                    mma8(sacc[nt], qa[kc][0], qa[kc][1], qa[kc][2], qa[kc][3], b0, b1);
                }
            }

            // causal mask (only near the diagonal)
            if (k0 + 63 > qw0) {
                int r0 = qw0 + (lane >> 2);
#pragma unroll
                for (int nt = 0; nt < 8; nt++) {
                    int col = k0 + nt * 8 + 2 * (lane & 3);
                    if (col     > r0)     sacc[nt][0] = -1e30f;
                    if (col + 1 > r0)     sacc[nt][1] = -1e30f;
                    if (col     > r0 + 8) sacc[nt][2] = -1e30f;
                    if (col + 1 > r0 + 8) sacc[nt][3] = -1e30f;
                }
            }

            // online softmax per row-half
#pragma unroll
            for (int h = 0; h < 2; h++) {
                float mx = -1e30f;
#pragma unroll
                for (int nt = 0; nt < 8; nt++) {
                    mx = fmaxf(mx, sacc[nt][h * 2 + 0]);
                    mx = fmaxf(mx, sacc[nt][h * 2 + 1]);
                }
                mx = fmaxf(mx, __shfl_xor_sync(0xffffffffu, mx, 1));
                mx = fmaxf(mx, __shfl_xor_sync(0xffffffffu, mx, 2));
                float mnew = fmaxf(m_i[h], mx);
                float alpha = __expf(m_i[h] - mnew);
                float rs = 0.f;
#pragma unroll
                for (int nt = 0; nt < 8; nt++) {
                    float p0 = __expf(sacc[nt][h * 2 + 0] - mnew);
                    float p1 = __expf(sacc[nt][h * 2 + 1] - mnew);
                    sacc[nt][h * 2 + 0] = p0;
                    sacc[nt][h * 2 + 1] = p1;
                    rs += p0 + p1;
                }
                rs += __shfl_xor_sync(0xffffffffu, rs, 1);
                rs += __shfl_xor_sync(0xffffffffu, rs, 2);
                l_i[h] = l_i[h] * alpha + rs;
                m_i[h] = mnew;
#pragma unroll
                for (int nt = 0; nt < 8; nt++) {
                    oacc[nt][h * 2 + 0] *= alpha;
                    oacc[nt][h * 2 + 1] *= alpha;
                }
            }

            // P -> per-warp smem (tf32), then PV mma
            float* Pw = Psm + w * 16 * KSD;
#pragma unroll
            for (int nt = 0; nt < 8; nt++) {
                int col = nt * 8 + 2 * (lane & 3);
                float2 p0, p1;
                p0.x = f2tff(sacc[nt][0]); p0.y = f2tff(sacc[nt][1]);
                p1.x = f2tff(sacc[nt][2]); p1.y = f2tff(sacc[nt][3]);
                *(float2*)&Pw[(lane >> 2) * KSD + col] = p0;
                *(float2*)&Pw[((lane >> 2) + 8) * KSD + col] = p1;
            }
            __syncwarp();
            const uint32_t* Pwu = (const uint32_t*)Pw;
#pragma unroll
            for (int kc = 0; kc < 8; kc++) {
                uint32_t a0 = Pwu[(lane >> 2) * KSD + kc * 8 + (lane & 3)];
                uint32_t a1 = Pwu[((lane >> 2) + 8) * KSD + kc * 8 + (lane & 3)];
                uint32_t a2 = Pwu[(lane >> 2) * KSD + kc * 8 + 4 + (lane & 3)];
                uint32_t a3 = Pwu[((lane >> 2) + 8) * KSD + kc * 8 + 4 + (lane & 3)];
#pragma unroll
                for (int nt = 0; nt < 8; nt++) {
                    uint32_t b0 = Vu[(kc * 8 + (lane & 3)) * VSD + nt * 8 + (lane >> 2)];
                    uint32_t b1 = Vu[(kc * 8 + 4 + (lane & 3)) * VSD + nt * 8 + (lane >> 2)];
                    mma8(oacc[nt], a0, a1, a2, a3, b0, b1);
                }
            }
        }
    }

    // normalize + store to g_att [B,T,C]
    int bb = bh >> 4, hh = bh & (HH - 1);
#pragma unroll
    for (int h = 0; h < 2; h++) {
        int row = qw0 + (lane >> 2) + h * 8;
        float inv = 1.f / l_i[h];
#pragma unroll
        for (int nt = 0; nt < 8; nt++) {
            int col = hh * DD + nt * 8 + 2 * (lane & 3);
            float2 r;
            r.x = oacc[nt][h * 2 + 0] * inv;
            r.y = oacc[nt][h * 2 + 1] * inv;
            *(float2*)(g_att + ((size_t)bb * TT + row) * CC + col) = r;
        }
    }
}

// ===========================================================================
// Launch
// ===========================================================================
extern "C" void kernel_launch(void* const* d_in, const int* in_sizes, int n_in,
                              void* d_out, int out_size)
{
    (void)in_sizes; (void)n_in; (void)out_size;
    const float* x      = (const float*)d_in[0];
    const float* qkv_w  = (const float*)d_in[1];
    const float* qkv_b  = (const float*)d_in[2];
    const float* proj_w = (const float*)d_in[3];
    const float* proj_b = (const float*)d_in[4];
    float* out = (float*)d_out;

    cudaFuncSetAttribute(attn_tc,
                         cudaFuncAttributeMaxDynamicSharedMemorySize, SMEM_ATTN);

    // 1) QKV projection + bias -> scatter [3][B,H,T,D]
    gemm_tc<<<dim3(3 * CC / GBN, BB * TT / GBM), 256>>>(
        x, qkv_w, qkv_b, nullptr, BB * TT, 3 * CC, CC, 1);

    // 2) Causal flash attention -> g_att [B,T,C]
    attn_tc<<<dim3(TT / 128, BB * HH), 256, SMEM_ATTN>>>();

    // 3) Output projection + bias -> d_out
    gemm_tc<<<dim3(CC / GBN, BB * TT / GBM), 256>>>(
        nullptr, proj_w, proj_b, out, BB * TT, CC, CC, 2);
}

// round 3
// speedup vs baseline: 2.7903x; 1.3278x over previous
#include <cuda_runtime.h>
#include <cuda_bf16.h>
#include <stdint.h>
#include <math.h>

// Problem constants
#define BB   4
#define TT   2048
#define CC   1024
#define HH   16
#define DD   64
#define BHTD (BB * HH * TT * DD)

// Scratch (device globals: alloc-free per harness rules)
__device__ float g_qkv[3ull * BHTD];            // [3][B,H,T,D]
__device__ float g_att[(size_t)BB * TT * CC];   // [B,T,C]

// ---------------------------------------------------------------------------
// tf32 / mma / cp.async helpers
// ---------------------------------------------------------------------------
__device__ __forceinline__ uint32_t f2tf(float x) {
    uint32_t u;
    asm("cvt.rna.tf32.f32 %0, %1;" : "=r"(u) : "f"(x));
    return u;
}
__device__ __forceinline__ float f2tff(float x) { return __uint_as_float(f2tf(x)); }

__device__ __forceinline__ void mma8(float* c,
    uint32_t a0, uint32_t a1, uint32_t a2, uint32_t a3,
    uint32_t b0, uint32_t b1)
{
    asm volatile(
        "mma.sync.aligned.m16n8k8.row.col.f32.tf32.tf32.f32 "
        "{%0,%1,%2,%3},{%4,%5,%6,%7},{%8,%9},{%0,%1,%2,%3};"
        : "+f"(c[0]), "+f"(c[1]), "+f"(c[2]), "+f"(c[3])
        : "r"(a0), "r"(a1), "r"(a2), "r"(a3), "r"(b0), "r"(b1));
}

__device__ __forceinline__ void cp16(uint32_t smem, const void* gmem) {
    asm volatile("cp.async.ca.shared.global [%0], [%1], 16;\n"
                 :: "r"(smem), "l"(gmem));
}
__device__ __forceinline__ void cp_commit() {
    asm volatile("cp.async.commit_group;\n" ::: "memory");
}
template <int N>
__device__ __forceinline__ void cp_wait() {
    asm volatile("cp.async.wait_group %0;\n" :: "n"(N) : "memory");
}

// ===========================================================================
// TF32 tensor-core GEMM v2: C[m,n] = sum_k A[m,k]*Bt[n,k] + bias[n]
// Block 128x128x32, 128 threads = 4 warps, warp tile 64x64.
// Smem: [m][k] raw fp32, 32-float rows, quad XOR swizzle; 2-stage cp.async.
// cvt -> tf32 at fragment load (rna).
// mode 0: plain store; mode 1: QKV scatter; mode 2: A := g_att.
// ===========================================================================
#define GBM 128
#define GBN 128
#define GBK 32
#define STG_FLOATS (GBM * GBK)                 // 4096 floats = 16KB per buffer
#define SMEM_GEMM  (2 * 2 * STG_FLOATS * 4)    // 2 stages x (A+B) = 64KB

// swizzled float index within a [128][32] tile
__device__ __forceinline__ int swz(int r, int c) {
    return r * 32 + ((((c >> 2)) ^ (r & 7)) << 2) + (c & 3);
}

__global__ __launch_bounds__(128) void gemm_tc(
    const float* __restrict__ Ain, const float* __restrict__ Bt,
    const float* __restrict__ bias, float* __restrict__ Cout,
    int M, int N, int K, int mode)
{
    extern __shared__ float smem[];
    const float* A = (mode == 2) ? g_att : Ain;

    int tid = threadIdx.x, lane = tid & 31, w = tid >> 5;
    int wm0 = (w >> 1) * 64;      // 2 warps along M
    int wn0 = (w & 1) * 64;       // 2 warps along N
    int m0 = blockIdx.y * GBM, n0 = blockIdx.x * GBN;

    uint32_t smem_base = (uint32_t)__cvta_generic_to_shared(smem);

    float acc[4][8][4];
#pragma unroll
    for (int mt = 0; mt < 4; mt++)
#pragma unroll
        for (int nt = 0; nt < 8; nt++)
#pragma unroll
            for (int j = 0; j < 4; j++) acc[mt][nt][j] = 0.f;

    // staging coords for this thread (8 x 16B per buffer)
    int srow[8], sq[8];
#pragma unroll
    for (int it = 0; it < 8; it++) {
        int l = tid + it * 128;       // 0..1023
        srow[it] = l >> 3;
        sq[it]   = l & 7;
    }

    int nK = K / GBK;

    // prologue: stage 0
    {
        uint32_t sA = smem_base;                      // stage 0 A
        uint32_t sB = smem_base + STG_FLOATS * 4;     // stage 0 B
#pragma unroll
        for (int it = 0; it < 8; it++) {
            int row = srow[it], q = sq[it];
            int soff = (row * 32 + ((q ^ (row & 7)) << 2)) * 4;
            cp16(sA + soff, A  + (size_t)(m0 + row) * K + q * 4);
            cp16(sB + soff, Bt + (size_t)(n0 + row) * K + q * 4);
        }
        cp_commit();
    }

    for (int kt = 0; kt < nK; kt++) {
        // issue next stage
        if (kt + 1 < nK) {
            int st = (kt + 1) & 1;
            int kk = (kt + 1) * GBK;
            uint32_t sA = smem_base + (size_t)st * 2 * STG_FLOATS * 4;
            uint32_t sB = sA + STG_FLOATS * 4;
#pragma unroll
            for (int it = 0; it < 8; it++) {
                int row = srow[it], q = sq[it];
                int soff = (row * 32 + ((q ^ (row & 7)) << 2)) * 4;
                cp16(sA + soff, A  + (size_t)(m0 + row) * K + kk + q * 4);
                cp16(sB + soff, Bt + (size_t)(n0 + row) * K + kk + q * 4);
            }
            cp_commit();
            cp_wait<1>();
        } else {
            cp_wait<0>();
        }
        __syncthreads();

        const float* As = smem + (size_t)(kt & 1) * 2 * STG_FLOATS;
        const float* Bs = As + STG_FLOATS;

#pragma unroll
        for (int kc = 0; kc < 4; kc++) {
            uint32_t a[4][4];
#pragma unroll
            for (int mt = 0; mt < 4; mt++) {
                int r = wm0 + mt * 16 + (lane >> 2);
                int c = kc * 8 + (lane & 3);
                a[mt][0] = f2tf(As[swz(r,     c)]);
                a[mt][1] = f2tf(As[swz(r + 8, c)]);
                a[mt][2] = f2tf(As[swz(r,     c + 4)]);
                a[mt][3] = f2tf(As[swz(r + 8, c + 4)]);
            }
#pragma unroll
            for (int nt = 0; nt < 8; nt++) {
                int n = wn0 + nt * 8 + (lane >> 2);
                int c = kc * 8 + (lane & 3);
                uint32_t b0 = f2tf(Bs[swz(n, c)]);
                uint32_t b1 = f2tf(Bs[swz(n, c + 4)]);
#pragma unroll
                for (int mt = 0; mt < 4; mt++)
                    mma8(acc[mt][nt], a[mt][0], a[mt][1], a[mt][2], a[mt][3], b0, b1);
            }
        }
        __syncthreads();
    }

    // Epilogue: bias + store
#pragma unroll
    for (int mt = 0; mt < 4; mt++) {
#pragma unroll
        for (int h = 0; h < 2; h++) {
            int m = m0 + wm0 + mt * 16 + (lane >> 2) + h * 8;
#pragma unroll
            for (int nt = 0; nt < 8; nt++) {
                int n = n0 + wn0 + nt * 8 + 2 * (lane & 3);
                float2 r;
                r.x = acc[mt][nt][h * 2 + 0] + bias[n];
                r.y = acc[mt][nt][h * 2 + 1] + bias[n + 1];
                if (mode == 1) {
                    int which = n >> 10;
                    int hh = (n >> 6) & (HH - 1);
                    int d = n & (DD - 1);
                    int b = m >> 11;
                    int t = m & (TT - 1);
                    float* p = g_qkv + (size_t)which * BHTD
                             + ((((size_t)b * HH + hh) * TT + t) * DD + d);
                    *(float2*)p = r;
                } else {
                    *(float2*)(Cout + (size_t)m * N + n) = r;
                }
            }
        }
    }
}

// ===========================================================================
// Flash attention (causal) with tf32 tensor cores. (unchanged from R2)
// ===========================================================================
#define KSD 68
#define VSD 72
#define SMEM_ATTN ((64 * KSD + 64 * VSD + 8 * 16 * KSD) * 4)

__global__ __launch_bounds__(256) void attn_tc()
{
    extern __shared__ float sm[];
    float* Ksm = sm;
    float* Vsm = sm + 64 * KSD;
    float* Psm = sm + 64 * KSD + 64 * VSD;
    const uint32_t* Ku = (const uint32_t*)Ksm;
    const uint32_t* Vu = (const uint32_t*)Vsm;

    int qb = gridDim.x - 1 - blockIdx.x;
    int bh = blockIdx.y;
    int q0 = qb * 128;
    int tid = threadIdx.x, lane = tid & 31, w = tid >> 5;
    int qw0 = q0 + w * 16;

    const float* qp = g_qkv + (size_t)bh * TT * DD;
    const float* kp = qp + (size_t)BHTD;
    const float* vp = qp + 2ull * BHTD;

    uint32_t qa[8][4];
    {
        int r = qw0 + (lane >> 2);
#pragma unroll
        for (int c = 0; c < 8; c++) {
            int col = c * 8 + (lane & 3);
            qa[c][0] = f2tf(qp[(size_t)r * DD + col] * 0.125f);
            qa[c][1] = f2tf(qp[(size_t)(r + 8) * DD + col] * 0.125f);
            qa[c][2] = f2tf(qp[(size_t)r * DD + col + 4] * 0.125f);
            qa[c][3] = f2tf(qp[(size_t)(r + 8) * DD + col + 4] * 0.125f);
        }
    }

    float m_i[2] = {-1e30f, -1e30f}, l_i[2] = {0.f, 0.f};
    float oacc[8][4];
#pragma unroll
    for (int nt = 0; nt < 8; nt++)
#pragma unroll
        for (int j = 0; j < 4; j++) oacc[nt][j] = 0.f;

    int jbmax = 2 * qb + 1;
    for (int jb = 0; jb <= jbmax; jb++) {
        int k0 = jb * 64;
        __syncthreads();
#pragma unroll
        for (int it = 0; it < 4; it++) {
            int l = tid + it * 256;
            int row = l >> 4;
            int dq = (l & 15) * 4;
            float4 kv = *(const float4*)(kp + (size_t)(k0 + row) * DD + dq);
            float4 kc;
            kc.x = f2tff(kv.x); kc.y = f2tff(kv.y);
            kc.z = f2tff(kv.z); kc.w = f2tff(kv.w);
            *(float4*)&Ksm[row * KSD + dq] = kc;
            float4 vv = *(const float4*)(vp + (size_t)(k0 + row) * DD + dq);
            float4 vc;
            vc.x = f2tff(vv.x); vc.y = f2tff(vv.y);
            vc.z = f2tff(vv.z); vc.w = f2tff(vv.w);
            *(float4*)&Vsm[row * VSD + dq] = vc;
        }
        __syncthreads();

        if (k0 <= qw0 + 15) {
            float sacc[8][4];
#pragma unroll
            for (int nt = 0; nt < 8; nt++)
#pragma unroll
                for (int j = 0; j < 4; j++) sacc[nt][j] = 0.f;
#pragma unroll
            for (int kc = 0; kc < 8; kc++) {
#pragma unroll
                for (int nt = 0; nt < 8; nt++) {
                    uint32_t b0 = Ku[(nt * 8 + (lane >> 2)) * KSD + kc * 8 + (lane & 3)];
                    uint32_t b1 = Ku[(nt * 8 + (lane >> 2)) * KSD + kc * 8 + 4 + (lane & 3)];
                    mma8(sacc[nt], qa[kc][0], qa[kc][1], qa[kc][2], qa[kc][3], b0, b1);
                }
            }

            if (k0 + 63 > qw0) {
                int r0 = qw0 + (lane >> 2);
#pragma unroll
                for (int nt = 0; nt < 8; nt++) {
                    int col = k0 + nt * 8 + 2 * (lane & 3);
                    if (col     > r0)     sacc[nt][0] = -1e30f;
                    if (col + 1 > r0)     sacc[nt][1] = -1e30f;
                    if (col     > r0 + 8) sacc[nt][2] = -1e30f;
                    if (col + 1 > r0 + 8) sacc[nt][3] = -1e30f;
                }
            }

#pragma unroll
            for (int h = 0; h < 2; h++) {
                float mx = -1e30f;
#pragma unroll
                for (int nt = 0; nt < 8; nt++) {
                    mx = fmaxf(mx, sacc[nt][h * 2 + 0]);
                    mx = fmaxf(mx, sacc[nt][h * 2 + 1]);
                }
                mx = fmaxf(mx, __shfl_xor_sync(0xffffffffu, mx, 1));
                mx = fmaxf(mx, __shfl_xor_sync(0xffffffffu, mx, 2));
                float mnew = fmaxf(m_i[h], mx);
                float alpha = __expf(m_i[h] - mnew);
                float rs = 0.f;
#pragma unroll
                for (int nt = 0; nt < 8; nt++) {
                    float p0 = __expf(sacc[nt][h * 2 + 0] - mnew);
                    float p1 = __expf(sacc[nt][h * 2 + 1] - mnew);
                    sacc[nt][h * 2 + 0] = p0;
                    sacc[nt][h * 2 + 1] = p1;
                    rs += p0 + p1;
                }
                rs += __shfl_xor_sync(0xffffffffu, rs, 1);
                rs += __shfl_xor_sync(0xffffffffu, rs, 2);
                l_i[h] = l_i[h] * alpha + rs;
                m_i[h] = mnew;
#pragma unroll
                for (int nt = 0; nt < 8; nt++) {
                    oacc[nt][h * 2 + 0] *= alpha;
                    oacc[nt][h * 2 + 1] *= alpha;
                }
            }

            float* Pw = Psm + w * 16 * KSD;
#pragma unroll
            for (int nt = 0; nt < 8; nt++) {
                int col = nt * 8 + 2 * (lane & 3);
                float2 p0, p1;
                p0.x = f2tff(sacc[nt][0]); p0.y = f2tff(sacc[nt][1]);
                p1.x = f2tff(sacc[nt][2]); p1.y = f2tff(sacc[nt][3]);
                *(float2*)&Pw[(lane >> 2) * KSD + col] = p0;
                *(float2*)&Pw[((lane >> 2) + 8) * KSD + col] = p1;
            }
            __syncwarp();
            const uint32_t* Pwu = (const uint32_t*)Pw;
#pragma unroll
            for (int kc = 0; kc < 8; kc++) {
                uint32_t a0 = Pwu[(lane >> 2) * KSD + kc * 8 + (lane & 3)];
                uint32_t a1 = Pwu[((lane >> 2) + 8) * KSD + kc * 8 + (lane & 3)];
                uint32_t a2 = Pwu[(lane >> 2) * KSD + kc * 8 + 4 + (lane & 3)];
                uint32_t a3 = Pwu[((lane >> 2) + 8) * KSD + kc * 8 + 4 + (lane & 3)];
#pragma unroll
                for (int nt = 0; nt < 8; nt++) {
                    uint32_t b0 = Vu[(kc * 8 + (lane & 3)) * VSD + nt * 8 + (lane >> 2)];
                    uint32_t b1 = Vu[(kc * 8 + 4 + (lane & 3)) * VSD + nt * 8 + (lane >> 2)];
                    mma8(oacc[nt], a0, a1, a2, a3, b0, b1);
                }
            }
        }
    }

    int bb = bh >> 4, hh = bh & (HH - 1);
#pragma unroll
    for (int h = 0; h < 2; h++) {
        int row = qw0 + (lane >> 2) + h * 8;
        float inv = 1.f / l_i[h];
#pragma unroll
        for (int nt = 0; nt < 8; nt++) {
            int col = hh * DD + nt * 8 + 2 * (lane & 3);
            float2 r;
            r.x = oacc[nt][h * 2 + 0] * inv;
            r.y = oacc[nt][h * 2 + 1] * inv;
            *(float2*)(g_att + ((size_t)bb * TT + row) * CC + col) = r;
        }
    }
}

// ===========================================================================
// Launch
// ===========================================================================
extern "C" void kernel_launch(void* const* d_in, const int* in_sizes, int n_in,
                              void* d_out, int out_size)
{
    (void)in_sizes; (void)n_in; (void)out_size;
    const float* x      = (const float*)d_in[0];
    const float* qkv_w  = (const float*)d_in[1];
    const float* qkv_b  = (const float*)d_in[2];
    const float* proj_w = (const float*)d_in[3];
    const float* proj_b = (const float*)d_in[4];
    float* out = (float*)d_out;

    cudaFuncSetAttribute(gemm_tc,
                         cudaFuncAttributeMaxDynamicSharedMemorySize, SMEM_GEMM);
    cudaFuncSetAttribute(attn_tc,
                         cudaFuncAttributeMaxDynamicSharedMemorySize, SMEM_ATTN);

    // 1) QKV projection + bias -> scatter [3][B,H,T,D]
    gemm_tc<<<dim3(3 * CC / GBN, BB * TT / GBM), 128, SMEM_GEMM>>>(
        x, qkv_w, qkv_b, nullptr, BB * TT, 3 * CC, CC, 1);

    // 2) Causal flash attention -> g_att [B,T,C]
    attn_tc<<<dim3(TT / 128, BB * HH), 256, SMEM_ATTN>>>();

    // 3) Output projection + bias -> d_out
    gemm_tc<<<dim3(CC / GBN, BB * TT / GBM), 128, SMEM_GEMM>>>(
        nullptr, proj_w, proj_b, out, BB * TT, CC, CC, 2);
}

// round 4
// speedup vs baseline: 3.1595x; 1.1323x over previous
#include <cuda_runtime.h>
#include <cuda_bf16.h>
#include <stdint.h>
#include <math.h>

// Problem constants
#define BB   4
#define TT   2048
#define CC   1024
#define HH   16
#define DD   64
#define BHTD (BB * HH * TT * DD)

// Scratch (device globals: alloc-free per harness rules)
__device__ float g_qkv[3ull * BHTD];            // [3][B,H,T,D] tf32-valued
__device__ float g_att[(size_t)BB * TT * CC];   // [B,T,C] tf32-valued
__device__ float g_xt[(size_t)BB * TT * CC];    // tf32(x)
__device__ float g_wqkv[3 * CC * CC];           // tf32(qkv_w)
__device__ float g_wproj[CC * CC];              // tf32(proj_w)

// ---------------------------------------------------------------------------
// tf32 / mma / cp.async helpers
// ---------------------------------------------------------------------------
__device__ __forceinline__ uint32_t f2tf(float x) {
    uint32_t u;
    asm("cvt.rna.tf32.f32 %0, %1;" : "=r"(u) : "f"(x));
    return u;
}
__device__ __forceinline__ float f2tff(float x) { return __uint_as_float(f2tf(x)); }

__device__ __forceinline__ void mma8(float* c,
    uint32_t a0, uint32_t a1, uint32_t a2, uint32_t a3,
    uint32_t b0, uint32_t b1)
{
    asm volatile(
        "mma.sync.aligned.m16n8k8.row.col.f32.tf32.tf32.f32 "
        "{%0,%1,%2,%3},{%4,%5,%6,%7},{%8,%9},{%0,%1,%2,%3};"
        : "+f"(c[0]), "+f"(c[1]), "+f"(c[2]), "+f"(c[3])
        : "r"(a0), "r"(a1), "r"(a2), "r"(a3), "r"(b0), "r"(b1));
}

__device__ __forceinline__ void cp16(uint32_t smem, const void* gmem) {
    asm volatile("cp.async.ca.shared.global [%0], [%1], 16;\n"
                 :: "r"(smem), "l"(gmem));
}
__device__ __forceinline__ void cp_commit() {
    asm volatile("cp.async.commit_group;\n" ::: "memory");
}
template <int N>
__device__ __forceinline__ void cp_wait() {
    asm volatile("cp.async.wait_group %0;\n" :: "n"(N) : "memory");
}

// ---------------------------------------------------------------------------
// Pre-round a buffer to tf32-valued fp32 (grid-stride over float4)
// ---------------------------------------------------------------------------
__global__ __launch_bounds__(256) void cvt_tf32(
    const float4* __restrict__ in, float4* __restrict__ out, int n4)
{
    int i = blockIdx.x * blockDim.x + threadIdx.x;
    int stride = gridDim.x * blockDim.x;
    for (; i < n4; i += stride) {
        float4 v = in[i];
        float4 r;
        r.x = f2tff(v.x); r.y = f2tff(v.y);
        r.z = f2tff(v.z); r.w = f2tff(v.w);
        out[i] = r;
    }
}

// ===========================================================================
// TF32 tensor-core GEMM: C[m,n] = sum_k A[m,k]*Bt[n,k] + bias[n]
// Operands already tf32-valued -> inner loop is pure LDS + MMA.
// Block 128x128x32, 128 threads = 4 warps, warp tile 64x64, cp.async 2-stage.
// mode 1: A=g_xt, scatter tf32 into g_qkv; mode 2: A=g_att, plain fp32 store.
// ===========================================================================
#define GBM 128
#define GBN 128
#define GBK 32
#define STG_FLOATS (GBM * GBK)
#define SMEM_GEMM  (2 * 2 * STG_FLOATS * 4)

__device__ __forceinline__ int swz(int r, int c) {
    return r * 32 + ((((c >> 2)) ^ (r & 7)) << 2) + (c & 3);
}

__global__ __launch_bounds__(128) void gemm_tc(
    const float* __restrict__ Bt,
    const float* __restrict__ bias, float* __restrict__ Cout,
    int M, int N, int K, int mode)
{
    extern __shared__ float smem[];
    const float* A = (mode == 2) ? g_att : g_xt;

    int tid = threadIdx.x, lane = tid & 31, w = tid >> 5;
    int wm0 = (w >> 1) * 64;
    int wn0 = (w & 1) * 64;
    int m0 = blockIdx.y * GBM, n0 = blockIdx.x * GBN;

    uint32_t smem_base = (uint32_t)__cvta_generic_to_shared(smem);

    float acc[4][8][4];
#pragma unroll
    for (int mt = 0; mt < 4; mt++)
#pragma unroll
        for (int nt = 0; nt < 8; nt++)
#pragma unroll
            for (int j = 0; j < 4; j++) acc[mt][nt][j] = 0.f;

    int srow[8], sq[8];
#pragma unroll
    for (int it = 0; it < 8; it++) {
        int l = tid + it * 128;
        srow[it] = l >> 3;
        sq[it]   = l & 7;
    }

    int nK = K / GBK;

    {
        uint32_t sA = smem_base;
        uint32_t sB = smem_base + STG_FLOATS * 4;
#pragma unroll
        for (int it = 0; it < 8; it++) {
            int row = srow[it], q = sq[it];
            int soff = (row * 32 + ((q ^ (row & 7)) << 2)) * 4;
            cp16(sA + soff, A  + (size_t)(m0 + row) * K + q * 4);
            cp16(sB + soff, Bt + (size_t)(n0 + row) * K + q * 4);
        }
        cp_commit();
    }

    for (int kt = 0; kt < nK; kt++) {
        if (kt + 1 < nK) {
            int st = (kt + 1) & 1;
            int kk = (kt + 1) * GBK;
            uint32_t sA = smem_base + (size_t)st * 2 * STG_FLOATS * 4;
            uint32_t sB = sA + STG_FLOATS * 4;
#pragma unroll
            for (int it = 0; it < 8; it++) {
                int row = srow[it], q = sq[it];
                int soff = (row * 32 + ((q ^ (row & 7)) << 2)) * 4;
                cp16(sA + soff, A  + (size_t)(m0 + row) * K + kk + q * 4);
                cp16(sB + soff, Bt + (size_t)(n0 + row) * K + kk + q * 4);
            }
            cp_commit();
            cp_wait<1>();
        } else {
            cp_wait<0>();
        }
        __syncthreads();

        const uint32_t* As = (const uint32_t*)(smem + (size_t)(kt & 1) * 2 * STG_FLOATS);
        const uint32_t* Bs = As + STG_FLOATS;

#pragma unroll
        for (int kc = 0; kc < 4; kc++) {
            uint32_t a[4][4];
#pragma unroll
            for (int mt = 0; mt < 4; mt++) {
                int r = wm0 + mt * 16 + (lane >> 2);
                int c = kc * 8 + (lane & 3);
                a[mt][0] = As[swz(r,     c)];
                a[mt][1] = As[swz(r + 8, c)];
                a[mt][2] = As[swz(r,     c + 4)];
                a[mt][3] = As[swz(r + 8, c + 4)];
            }
#pragma unroll
            for (int nt = 0; nt < 8; nt++) {
                int n = wn0 + nt * 8 + (lane >> 2);
                int c = kc * 8 + (lane & 3);
                uint32_t b0 = Bs[swz(n, c)];
                uint32_t b1 = Bs[swz(n, c + 4)];
#pragma unroll
                for (int mt = 0; mt < 4; mt++)
                    mma8(acc[mt][nt], a[mt][0], a[mt][1], a[mt][2], a[mt][3], b0, b1);
            }
        }
        __syncthreads();
    }

    // Epilogue
#pragma unroll
    for (int mt = 0; mt < 4; mt++) {
#pragma unroll
        for (int h = 0; h < 2; h++) {
            int m = m0 + wm0 + mt * 16 + (lane >> 2) + h * 8;
#pragma unroll
            for (int nt = 0; nt < 8; nt++) {
                int n = n0 + wn0 + nt * 8 + 2 * (lane & 3);
                float2 r;
                r.x = acc[mt][nt][h * 2 + 0] + bias[n];
                r.y = acc[mt][nt][h * 2 + 1] + bias[n + 1];
                if (mode == 1) {
                    r.x = f2tff(r.x);          // pre-round for attention
                    r.y = f2tff(r.y);
                    int which = n >> 10;
                    int hh = (n >> 6) & (HH - 1);
                    int d = n & (DD - 1);
                    int b = m >> 11;
                    int t = m & (TT - 1);
                    float* p = g_qkv + (size_t)which * BHTD
                             + ((((size_t)b * HH + hh) * TT + t) * DD + d);
                    *(float2*)p = r;
                } else {
                    *(float2*)(Cout + (size_t)m * N + n) = r;
                }
            }
        }
    }
}

// ===========================================================================
// Flash attention (causal), tf32 tensor cores, cp.async K/V double buffer.
// Q/K/V already tf32-valued. Grid (T/128, B*H), 256 thr = 8 warps x 16 rows.
// ===========================================================================
#define KSD 68
#define VSD 72
#define KVSTG (64 * KSD + 64 * VSD)            // floats per stage
#define SMEM_ATTN ((2 * KVSTG + 8 * 16 * KSD) * 4)

__global__ __launch_bounds__(256) void attn_tc()
{
    extern __shared__ float sm[];
    float* Psm = sm + 2 * KVSTG;

    int qb = gridDim.x - 1 - blockIdx.x;
    int bh = blockIdx.y;
    int q0 = qb * 128;
    int tid = threadIdx.x, lane = tid & 31, w = tid >> 5;
    int qw0 = q0 + w * 16;

    const float* qp = g_qkv + (size_t)bh * TT * DD;
    const float* kp = qp + (size_t)BHTD;
    const float* vp = qp + 2ull * BHTD;

    uint32_t smem_base = (uint32_t)__cvta_generic_to_shared(sm);

    // staging coords: 64 rows x 16 chunks per tile, 4 chunks/thread each of K,V
    int srow[4], sdq[4];
#pragma unroll
    for (int it = 0; it < 4; it++) {
        int l = tid + it * 256;
        srow[it] = l >> 4;
        sdq[it]  = (l & 15) * 4;
    }

    // prologue: stage 0 <- k-block 0
    {
        uint32_t kb = smem_base;
        uint32_t vb = smem_base + 64 * KSD * 4;
#pragma unroll
        for (int it = 0; it < 4; it++) {
            int row = srow[it], dq = sdq[it];
            cp16(kb + (row * KSD + dq) * 4, kp + (size_t)row * DD + dq);
            cp16(vb + (row * VSD + dq) * 4, vp + (size_t)row * DD + dq);
        }
        cp_commit();
    }

    // Q -> registers as A-fragments (x0.125 exact on tf32 grid)
    uint32_t qa[8][4];
    {
        int r = qw0 + (lane >> 2);
#pragma unroll
        for (int c = 0; c < 8; c++) {
            int col = c * 8 + (lane & 3);
            qa[c][0] = __float_as_uint(qp[(size_t)r * DD + col] * 0.125f);
            qa[c][1] = __float_as_uint(qp[(size_t)(r + 8) * DD + col] * 0.125f);
            qa[c][2] = __float_as_uint(qp[(size_t)r * DD + col + 4] * 0.125f);
            qa[c][3] = __float_as_uint(qp[(size_t)(r + 8) * DD + col + 4] * 0.125f);
        }
    }

    float m_i[2] = {-1e30f, -1e30f}, l_i[2] = {0.f, 0.f};
    float oacc[8][4];
#pragma unroll
    for (int nt = 0; nt < 8; nt++)
#pragma unroll
        for (int j = 0; j < 4; j++) oacc[nt][j] = 0.f;

    int jbmax = 2 * qb + 1;
    for (int jb = 0; jb <= jbmax; jb++) {
        int k0 = jb * 64;
        cp_wait<0>();
        __syncthreads();   // data ready + everyone done with other stage

        // prefetch next k-block into other stage
        if (jb < jbmax) {
            int k1 = k0 + 64;
            uint32_t kb = smem_base + (size_t)((jb + 1) & 1) * KVSTG * 4;
            uint32_t vb = kb + 64 * KSD * 4;
#pragma unroll
            for (int it = 0; it < 4; it++) {
                int row = srow[it], dq = sdq[it];
                cp16(kb + (row * KSD + dq) * 4, kp + (size_t)(k1 + row) * DD + dq);
                cp16(vb + (row * VSD + dq) * 4, vp + (size_t)(k1 + row) * DD + dq);
            }
            cp_commit();
        }

        const uint32_t* Ku = (const uint32_t*)(sm + (size_t)(jb & 1) * KVSTG);
        const uint32_t* Vu = Ku + 64 * KSD;

        if (k0 <= qw0 + 15) {
            float sacc[8][4];
#pragma unroll
            for (int nt = 0; nt < 8; nt++)
#pragma unroll
                for (int j = 0; j < 4; j++) sacc[nt][j] = 0.f;
#pragma unroll
            for (int kc = 0; kc < 8; kc++) {
#pragma unroll
                for (int nt = 0; nt < 8; nt++) {
                    uint32_t b0 = Ku[(nt * 8 + (lane >> 2)) * KSD + kc * 8 + (lane & 3)];
                    uint32_t b1 = Ku[(nt * 8 + (lane >> 2)) * KSD + kc * 8 + 4 + (lane & 3)];
                    mma8(sacc[nt], qa[kc][0], qa[kc][1], qa[kc][2], qa[kc][3], b0, b1);
                }
            }

            if (k0 + 63 > qw0) {
                int r0 = qw0 + (lane >> 2);
#pragma unroll
                for (int nt = 0; nt < 8; nt++) {
                    int col = k0 + nt * 8 + 2 * (lane & 3);
                    if (col     > r0)     sacc[nt][0] = -1e30f;
                    if (col + 1 > r0)     sacc[nt][1] = -1e30f;
                    if (col     > r0 + 8) sacc[nt][2] = -1e30f;
                    if (col + 1 > r0 + 8) sacc[nt][3] = -1e30f;
                }
            }

#pragma unroll
            for (int h = 0; h < 2; h++) {
                float mx = -1e30f;
#pragma unroll
                for (int nt = 0; nt < 8; nt++) {
                    mx = fmaxf(mx, sacc[nt][h * 2 + 0]);
                    mx = fmaxf(mx, sacc[nt][h * 2 + 1]);
                }
                mx = fmaxf(mx, __shfl_xor_sync(0xffffffffu, mx, 1));
                mx = fmaxf(mx, __shfl_xor_sync(0xffffffffu, mx, 2));
                float mnew = fmaxf(m_i[h], mx);
                float alpha = __expf(m_i[h] - mnew);
                float rs = 0.f;
#pragma unroll
                for (int nt = 0; nt < 8; nt++) {
                    float p0 = __expf(sacc[nt][h * 2 + 0] - mnew);
                    float p1 = __expf(sacc[nt][h * 2 + 1] - mnew);
                    sacc[nt][h * 2 + 0] = p0;
                    sacc[nt][h * 2 + 1] = p1;
                    rs += p0 + p1;
                }
                rs += __shfl_xor_sync(0xffffffffu, rs, 1);
                rs += __shfl_xor_sync(0xffffffffu, rs, 2);
                l_i[h] = l_i[h] * alpha + rs;
                m_i[h] = mnew;
#pragma unroll
                for (int nt = 0; nt < 8; nt++) {
                    oacc[nt][h * 2 + 0] *= alpha;
                    oacc[nt][h * 2 + 1] *= alpha;
                }
            }

            float* Pw = Psm + w * 16 * KSD;
#pragma unroll
            for (int nt = 0; nt < 8; nt++) {
                int col = nt * 8 + 2 * (lane & 3);
                float2 p0, p1;
                p0.x = f2tff(sacc[nt][0]); p0.y = f2tff(sacc[nt][1]);
                p1.x = f2tff(sacc[nt][2]); p1.y = f2tff(sacc[nt][3]);
                *(float2*)&Pw[(lane >> 2) * KSD + col] = p0;
                *(float2*)&Pw[((lane >> 2) + 8) * KSD + col] = p1;
            }
            __syncwarp();
            const uint32_t* Pwu = (const uint32_t*)Pw;
#pragma unroll
            for (int kc = 0; kc < 8; kc++) {
                uint32_t a0 = Pwu[(lane >> 2) * KSD + kc * 8 + (lane & 3)];
                uint32_t a1 = Pwu[((lane >> 2) + 8) * KSD + kc * 8 + (lane & 3)];
                uint32_t a2 = Pwu[(lane >> 2) * KSD + kc * 8 + 4 + (lane & 3)];
                uint32_t a3 = Pwu[((lane >> 2) + 8) * KSD + kc * 8 + 4 + (lane & 3)];
#pragma unroll
                for (int nt = 0; nt < 8; nt++) {
                    uint32_t b0 = Vu[(kc * 8 + (lane & 3)) * VSD + nt * 8 + (lane >> 2)];
                    uint32_t b1 = Vu[(kc * 8 + 4 + (lane & 3)) * VSD + nt * 8 + (lane >> 2)];
                    mma8(oacc[nt], a0, a1, a2, a3, b0, b1);
                }
            }
        }
        __syncthreads();   // all compute on this stage done before overwrite
    }

    int bb = bh >> 4, hh = bh & (HH - 1);
#pragma unroll
    for (int h = 0; h < 2; h++) {
        int row = qw0 + (lane >> 2) + h * 8;
        float inv = 1.f / l_i[h];
#pragma unroll
        for (int nt = 0; nt < 8; nt++) {
            int col = hh * DD + nt * 8 + 2 * (lane & 3);
            float2 r;
            r.x = f2tff(oacc[nt][h * 2 + 0] * inv);   // pre-round for proj
            r.y = f2tff(oacc[nt][h * 2 + 1] * inv);
            *(float2*)(g_att + ((size_t)bb * TT + row) * CC + col) = r;
        }
    }
}

// ===========================================================================
// Launch
// ===========================================================================
extern "C" void kernel_launch(void* const* d_in, const int* in_sizes, int n_in,
                              void* d_out, int out_size)
{
    (void)in_sizes; (void)n_in; (void)out_size;
    const float* x      = (const float*)d_in[0];
    const float* qkv_w  = (const float*)d_in[1];
    const float* qkv_b  = (const float*)d_in[2];
    const float* proj_w = (const float*)d_in[3];
    const float* proj_b = (const float*)d_in[4];
    float* out = (float*)d_out;

    cudaFuncSetAttribute(gemm_tc,
                         cudaFuncAttributeMaxDynamicSharedMemorySize, SMEM_GEMM);
    cudaFuncSetAttribute(attn_tc,
                         cudaFuncAttributeMaxDynamicSharedMemorySize, SMEM_ATTN);

    float* xt; float* wq; float* wp;
    cudaGetSymbolAddress((void**)&xt, g_xt);
    cudaGetSymbolAddress((void**)&wq, g_wqkv);
    cudaGetSymbolAddress((void**)&wp, g_wproj);

    // 0) pre-round operands to tf32 grid
    cvt_tf32<<<2048, 256>>>((const float4*)x,      (float4*)xt, BB * TT * CC / 4);
    cvt_tf32<<<1024, 256>>>((const float4*)qkv_w,  (float4*)wq, 3 * CC * CC / 4);
    cvt_tf32<<<512,  256>>>((const float4*)proj_w, (float4*)wp, CC * CC / 4);

    // 1) QKV projection + bias -> scatter tf32 [3][B,H,T,D]
    gemm_tc<<<dim3(3 * CC / GBN, BB * TT / GBM), 128, SMEM_GEMM>>>(
        wq, qkv_b, nullptr, BB * TT, 3 * CC, CC, 1);

    // 2) Causal flash attention -> g_att [B,T,C]
    attn_tc<<<dim3(TT / 128, BB * HH), 256, SMEM_ATTN>>>();

    // 3) Output projection + bias -> d_out
    gemm_tc<<<dim3(CC / GBN, BB * TT / GBM), 128, SMEM_GEMM>>>(
        wp, proj_b, out, BB * TT, CC, CC, 2);
}